// round 1
// baseline (speedup 1.0000x reference)
#include <cuda_runtime.h>
#include <cuda_bf16.h>
#include <math.h>

// Problem shape (fixed for this bench instance):
//   query/key/value: (B*H, N, DK) f32 ; relation: (B, N, N, DK) f32
//   mask: (B, H, N, N) f32 ; out: (B*H, N, DK) f32
#define BB 4
#define HH 8
#define NN 512
#define DKK 64
#define SCALE 0.125f   // 1/sqrt(64)

// ---------------- packed f32x2 helpers (FFMA2 on sm_103a) ----------------
__device__ __forceinline__ unsigned long long f2u(float2 a) {
    unsigned long long r;
    asm("mov.b64 %0, {%1, %2};" : "=l"(r) : "f"(a.x), "f"(a.y));
    return r;
}
__device__ __forceinline__ float2 u2f(unsigned long long a) {
    float2 r;
    asm("mov.b64 {%0, %1}, %2;" : "=f"(r.x), "=f"(r.y) : "l"(a));
    return r;
}
__device__ __forceinline__ float2 ffma2(float2 a, float2 b, float2 c) {
    unsigned long long r;
    asm("fma.rn.f32x2 %0, %1, %2, %3;"
        : "=l"(r) : "l"(f2u(a)), "l"(f2u(b)), "l"(f2u(c)));
    return u2f(r);
}
__device__ __forceinline__ float2 fadd2(float2 a, float2 b) {
    unsigned long long r;
    asm("add.rn.f32x2 %0, %1, %2;" : "=l"(r) : "l"(f2u(a)), "l"(f2u(b)));
    return u2f(r);
}
__device__ __forceinline__ float2 lo2(float4 v) { return make_float2(v.x, v.y); }
__device__ __forceinline__ float2 hi2(float4 v) { return make_float2(v.z, v.w); }

// SMEM score row padding: +4 floats so 8 head-rows land on distinct banks
#define SPAD (NN + 4)

__global__ __launch_bounds__(256, 2)
void rel_attn_kernel(const float* __restrict__ q,
                     const float* __restrict__ k,
                     const float* __restrict__ v,
                     const float* __restrict__ rel,
                     const float* __restrict__ mask,
                     float* __restrict__ out) {
    __shared__ float s_s[HH][SPAD];     // scores, then unnormalized exp(p)
    __shared__ float red[8][HH * DKK];  // per-warp phase-2 partials
    __shared__ float inv_s[HH];

    const int bid  = blockIdx.x;
    const int b    = bid >> 9;          // / NN
    const int i    = bid & (NN - 1);
    const int tid  = threadIdx.x;
    const int warp = tid >> 5;
    const int lane = tid & 31;

    // =============== Phase 1: s[h][j] = q[h]·(scale*k[h,j] + rel[i,j]) ======
    {
        const int dd = lane & 7;   // which 8-float d-octet this lane owns
        const int jj = lane >> 3;  // which of 4 j's in the warp's group

        // Preload q[h][dd*8 .. dd*8+7] into registers (shared by all j steps)
        float4 qa[HH], qb[HH];
#pragma unroll
        for (int h = 0; h < HH; h++) {
            const float* qp = q + ((size_t)(b * HH + h) * NN + i) * DKK + dd * 8;
            qa[h] = *(const float4*)qp;
            qb[h] = *(const float4*)(qp + 4);
        }
        const float2 sc2 = make_float2(SCALE, SCALE);
        const float* relrow = rel + (((size_t)b * NN + i) * NN) * DKK;

        for (int s = warp; s < NN / 4; s += 8) {
            const int j = s * 4 + jj;
            const float* rp = relrow + (size_t)j * DKK + dd * 8;
            const float4 ra = *(const float4*)rp;
            const float4 rb = *(const float4*)(rp + 4);

            float2 acc[HH];
#pragma unroll
            for (int h = 0; h < HH; h++) {
                const float* kp = k + ((size_t)(b * HH + h) * NN + j) * DKK + dd * 8;
                const float4 ka = *(const float4*)kp;
                const float4 kb = *(const float4*)(kp + 4);
                // e = scale*k + rel  (per element)
                float2 e0 = ffma2(lo2(ka), sc2, lo2(ra));
                float2 e1 = ffma2(hi2(ka), sc2, hi2(ra));
                float2 e2 = ffma2(lo2(kb), sc2, lo2(rb));
                float2 e3 = ffma2(hi2(kb), sc2, hi2(rb));
                float2 a  = ffma2(lo2(qa[h]), e0, make_float2(0.f, 0.f));
                a = ffma2(hi2(qa[h]), e1, a);
                a = ffma2(lo2(qb[h]), e2, a);
                a = ffma2(hi2(qb[h]), e3, a);
                acc[h] = a;
            }
#pragma unroll
            for (int h = 0; h < HH; h++) {
                float r = acc[h].x + acc[h].y;
                r += __shfl_xor_sync(0xffffffffu, r, 1);
                r += __shfl_xor_sync(0xffffffffu, r, 2);
                r += __shfl_xor_sync(0xffffffffu, r, 4);
                if (dd == 0) s_s[h][j] = r;
            }
        }
    }
    __syncthreads();

    // =============== Softmax (warp w owns head h=w), mask added here ========
    {
        const int h = warp;
        const float* mp = mask + (((size_t)b * HH + h) * NN + i) * NN;
        float vals[16];
        float mx = -3.4e38f;
#pragma unroll
        for (int t = 0; t < 16; t++) {
            const int j = t * 32 + lane;
            float x = s_s[h][j] + mp[j];
            vals[t] = x;
            mx = fmaxf(mx, x);
        }
#pragma unroll
        for (int o = 16; o > 0; o >>= 1)
            mx = fmaxf(mx, __shfl_xor_sync(0xffffffffu, mx, o));
        float sum = 0.f;
#pragma unroll
        for (int t = 0; t < 16; t++) {
            float e = __expf(vals[t] - mx);
            sum += e;
            s_s[h][t * 32 + lane] = e;   // unnormalized
        }
#pragma unroll
        for (int o = 16; o > 0; o >>= 1)
            sum += __shfl_xor_sync(0xffffffffu, sum, o);
        if (lane == 0) inv_s[h] = 1.0f / sum;
    }
    __syncthreads();

    // =============== Phase 2: out[h][d] = Σ_j p[h][j]*(v[h,j,d]+rel[i,j,d]) =
    {
        const int h2 = lane >> 2;     // head owned by this lane
        const int dl = lane & 3;      // d-quarter (16 floats)
        const float* vbase = v + ((size_t)(b * HH + h2) * NN) * DKK + dl * 16;
        const float* rbase = rel + (((size_t)b * NN + i) * NN) * DKK + dl * 16;

        float2 acc2[8];
#pragma unroll
        for (int t = 0; t < 8; t++) acc2[t] = make_float2(0.f, 0.f);

        const int j0 = warp * 64;
        for (int j = j0; j < j0 + 64; j++) {
            const float p = s_s[h2][j];
            const float2 p2 = make_float2(p, p);
            const float* vp = vbase + (size_t)j * DKK;
            const float* rp = rbase + (size_t)j * DKK;
#pragma unroll
            for (int t = 0; t < 4; t++) {
                const float4 v4 = *(const float4*)(vp + t * 4);
                const float4 r4 = *(const float4*)(rp + t * 4);
                float2 e0 = fadd2(lo2(v4), lo2(r4));
                float2 e1 = fadd2(hi2(v4), hi2(r4));
                acc2[2 * t]     = ffma2(p2, e0, acc2[2 * t]);
                acc2[2 * t + 1] = ffma2(p2, e1, acc2[2 * t + 1]);
            }
        }
        // stash this warp's partial
#pragma unroll
        for (int t = 0; t < 4; t++) {
            float4 o;
            o.x = acc2[2 * t].x;     o.y = acc2[2 * t].y;
            o.z = acc2[2 * t + 1].x; o.w = acc2[2 * t + 1].y;
            *(float4*)&red[warp][h2 * 64 + dl * 16 + t * 4] = o;
        }
    }
    __syncthreads();

    // =============== Cross-warp reduce + normalize + store ==================
    for (int idx = tid; idx < HH * DKK; idx += 256) {
        float sum = 0.f;
#pragma unroll
        for (int w = 0; w < 8; w++) sum += red[w][idx];
        const int h = idx >> 6;
        const int d = idx & 63;
        out[((size_t)(b * HH + h) * NN + i) * DKK + d] = sum * inv_s[h];
    }
}

extern "C" void kernel_launch(void* const* d_in, const int* in_sizes, int n_in,
                              void* d_out, int out_size) {
    const float* q    = (const float*)d_in[0];
    const float* k    = (const float*)d_in[1];
    const float* v    = (const float*)d_in[2];
    const float* rel  = (const float*)d_in[3];
    const float* mask = (const float*)d_in[4];
    // d_in[5] = head_num (device scalar) — shape is fixed, ignored
    float* out = (float*)d_out;

    rel_attn_kernel<<<BB * NN, 256>>>(q, k, v, rel, mask, out);
}

// round 2
// speedup vs baseline: 1.0045x; 1.0045x over previous
#include <cuda_runtime.h>
#include <cuda_bf16.h>
#include <math.h>

// Problem shape (fixed for this bench instance):
//   query/key/value: (B*H, N, DK) f32 ; relation: (B, N, N, DK) f32
//   mask: (B, H, N, N) f32 ; out: (B*H, N, DK) f32
#define BB 4
#define HH 8
#define NN 512
#define DKK 64
#define SCALE 0.125f   // 1/sqrt(64)

// ---------------- packed f32x2 helpers (FFMA2 on sm_103a) ----------------
__device__ __forceinline__ unsigned long long f2u(float2 a) {
    unsigned long long r;
    asm("mov.b64 %0, {%1, %2};" : "=l"(r) : "f"(a.x), "f"(a.y));
    return r;
}
__device__ __forceinline__ float2 u2f(unsigned long long a) {
    float2 r;
    asm("mov.b64 {%0, %1}, %2;" : "=f"(r.x), "=f"(r.y) : "l"(a));
    return r;
}
__device__ __forceinline__ float2 ffma2(float2 a, float2 b, float2 c) {
    unsigned long long r;
    asm("fma.rn.f32x2 %0, %1, %2, %3;"
        : "=l"(r) : "l"(f2u(a)), "l"(f2u(b)), "l"(f2u(c)));
    return u2f(r);
}
__device__ __forceinline__ float2 fadd2(float2 a, float2 b) {
    unsigned long long r;
    asm("add.rn.f32x2 %0, %1, %2;" : "=l"(r) : "l"(f2u(a)), "l"(f2u(b)));
    return u2f(r);
}
__device__ __forceinline__ float2 lo2(float4 v) { return make_float2(v.x, v.y); }
__device__ __forceinline__ float2 hi2(float4 v) { return make_float2(v.z, v.w); }

// SMEM score row padding: +4 floats so 8 head-rows land on distinct banks
#define SPAD (NN + 4)

__global__ __launch_bounds__(256, 2)
void rel_attn_kernel(const float* __restrict__ q,
                     const float* __restrict__ k,
                     const float* __restrict__ v,
                     const float* __restrict__ rel,
                     const float* __restrict__ mask,
                     float* __restrict__ out) {
    __shared__ float s_s[HH][SPAD];     // scores, then unnormalized exp(p)
    __shared__ float red[8][HH * DKK];  // per-warp phase-2 partials
    __shared__ float inv_s[HH];

    const int bid  = blockIdx.x;
    const int b    = bid >> 9;          // / NN
    const int i    = bid & (NN - 1);
    const int tid  = threadIdx.x;
    const int warp = tid >> 5;
    const int lane = tid & 31;

    // =============== Phase 1: s[h][j] = q[h]·(scale*k[h,j] + rel[i,j]) ======
    {
        const int dd = lane & 7;   // which 8-float d-octet this lane owns
        const int jj = lane >> 3;  // which of 4 j's in the warp's group

        // Preload q[h][dd*8 .. dd*8+7] into registers (shared by all j steps)
        float4 qa[HH], qb[HH];
#pragma unroll
        for (int h = 0; h < HH; h++) {
            const float* qp = q + ((size_t)(b * HH + h) * NN + i) * DKK + dd * 8;
            qa[h] = *(const float4*)qp;
            qb[h] = *(const float4*)(qp + 4);
        }
        const float2 sc2 = make_float2(SCALE, SCALE);
        const float* relrow = rel + (((size_t)b * NN + i) * NN) * DKK;

        for (int s = warp; s < NN / 4; s += 8) {
            const int j = s * 4 + jj;
            const float* rp = relrow + (size_t)j * DKK + dd * 8;
            const float4 ra = *(const float4*)rp;
            const float4 rb = *(const float4*)(rp + 4);

            float2 acc[HH];
#pragma unroll
            for (int h = 0; h < HH; h++) {
                const float* kp = k + ((size_t)(b * HH + h) * NN + j) * DKK + dd * 8;
                const float4 ka = *(const float4*)kp;
                const float4 kb = *(const float4*)(kp + 4);
                // e = scale*k + rel  (per element)
                float2 e0 = ffma2(lo2(ka), sc2, lo2(ra));
                float2 e1 = ffma2(hi2(ka), sc2, hi2(ra));
                float2 e2 = ffma2(lo2(kb), sc2, lo2(rb));
                float2 e3 = ffma2(hi2(kb), sc2, hi2(rb));
                float2 a  = ffma2(lo2(qa[h]), e0, make_float2(0.f, 0.f));
                a = ffma2(hi2(qa[h]), e1, a);
                a = ffma2(lo2(qb[h]), e2, a);
                a = ffma2(hi2(qb[h]), e3, a);
                acc[h] = a;
            }
#pragma unroll
            for (int h = 0; h < HH; h++) {
                float r = acc[h].x + acc[h].y;
                r += __shfl_xor_sync(0xffffffffu, r, 1);
                r += __shfl_xor_sync(0xffffffffu, r, 2);
                r += __shfl_xor_sync(0xffffffffu, r, 4);
                if (dd == 0) s_s[h][j] = r;
            }
        }
    }
    __syncthreads();

    // =============== Softmax (warp w owns head h=w), mask added here ========
    {
        const int h = warp;
        const float* mp = mask + (((size_t)b * HH + h) * NN + i) * NN;
        float vals[16];
        float mx = -3.4e38f;
#pragma unroll
        for (int t = 0; t < 16; t++) {
            const int j = t * 32 + lane;
            float x = s_s[h][j] + mp[j];
            vals[t] = x;
            mx = fmaxf(mx, x);
        }
#pragma unroll
        for (int o = 16; o > 0; o >>= 1)
            mx = fmaxf(mx, __shfl_xor_sync(0xffffffffu, mx, o));
        float sum = 0.f;
#pragma unroll
        for (int t = 0; t < 16; t++) {
            float e = __expf(vals[t] - mx);
            sum += e;
            s_s[h][t * 32 + lane] = e;   // unnormalized
        }
#pragma unroll
        for (int o = 16; o > 0; o >>= 1)
            sum += __shfl_xor_sync(0xffffffffu, sum, o);
        if (lane == 0) inv_s[h] = 1.0f / sum;
    }
    __syncthreads();

    // =============== Phase 2: out[h][d] = Σ_j p[h][j]*(v[h,j,d]+rel[i,j,d]) =
    {
        const int h2 = lane >> 2;     // head owned by this lane
        const int dl = lane & 3;      // d-quarter (16 floats)
        const float* vbase = v + ((size_t)(b * HH + h2) * NN) * DKK + dl * 16;
        const float* rbase = rel + (((size_t)b * NN + i) * NN) * DKK + dl * 16;

        float2 acc2[8];
#pragma unroll
        for (int t = 0; t < 8; t++) acc2[t] = make_float2(0.f, 0.f);

        const int j0 = warp * 64;
        for (int j = j0; j < j0 + 64; j++) {
            const float p = s_s[h2][j];
            const float2 p2 = make_float2(p, p);
            const float* vp = vbase + (size_t)j * DKK;
            const float* rp = rbase + (size_t)j * DKK;
#pragma unroll
            for (int t = 0; t < 4; t++) {
                const float4 v4 = *(const float4*)(vp + t * 4);
                const float4 r4 = *(const float4*)(rp + t * 4);
                float2 e0 = fadd2(lo2(v4), lo2(r4));
                float2 e1 = fadd2(hi2(v4), hi2(r4));
                acc2[2 * t]     = ffma2(p2, e0, acc2[2 * t]);
                acc2[2 * t + 1] = ffma2(p2, e1, acc2[2 * t + 1]);
            }
        }
        // stash this warp's partial
#pragma unroll
        for (int t = 0; t < 4; t++) {
            float4 o;
            o.x = acc2[2 * t].x;     o.y = acc2[2 * t].y;
            o.z = acc2[2 * t + 1].x; o.w = acc2[2 * t + 1].y;
            *(float4*)&red[warp][h2 * 64 + dl * 16 + t * 4] = o;
        }
    }
    __syncthreads();

    // =============== Cross-warp reduce + normalize + store ==================
    for (int idx = tid; idx < HH * DKK; idx += 256) {
        float sum = 0.f;
#pragma unroll
        for (int w = 0; w < 8; w++) sum += red[w][idx];
        const int h = idx >> 6;
        const int d = idx & 63;
        out[((size_t)(b * HH + h) * NN + i) * DKK + d] = sum * inv_s[h];
    }
}

extern "C" void kernel_launch(void* const* d_in, const int* in_sizes, int n_in,
                              void* d_out, int out_size) {
    const float* q    = (const float*)d_in[0];
    const float* k    = (const float*)d_in[1];
    const float* v    = (const float*)d_in[2];
    const float* rel  = (const float*)d_in[3];
    const float* mask = (const float*)d_in[4];
    // d_in[5] = head_num (device scalar) — shape is fixed, ignored
    float* out = (float*)d_out;

    rel_attn_kernel<<<BB * NN, 256>>>(q, k, v, rel, mask, out);
}

// round 3
// speedup vs baseline: 2.1114x; 2.1020x over previous
#include <cuda_runtime.h>
#include <cuda_bf16.h>
#include <math.h>

// Shapes fixed for this bench: B=4, H=8, N=512, DK=64
#define BB 4
#define HH 8
#define NN 512
#define DKK 64
#define TI 4                 // i-rows per CTA
#define SCALE 0.125f         // 1/sqrt(64)
#define SROW 516             // padded score row (bank-conflict-free h stride)

// smem layout in floats
#define S_OFF    0
#define RED1_OFF (TI*HH*SROW)                 // 16512
#define RED2_OFF (RED1_OFF + TI*HH*DKK)       // 18560
#define INV_OFF  (RED2_OFF + 2*TI*HH*DKK)     // 22656
#define SMEM_FLOATS (INV_OFF + TI*HH)         // 22688
#define SMEM_BYTES (SMEM_FLOATS * 4)          // 90752

// ---------------- packed f32x2 helpers (FFMA2 on sm_103a) ----------------
__device__ __forceinline__ unsigned long long f2u(float2 a) {
    unsigned long long r;
    asm("mov.b64 %0, {%1, %2};" : "=l"(r) : "f"(a.x), "f"(a.y));
    return r;
}
__device__ __forceinline__ float2 u2f(unsigned long long a) {
    float2 r;
    asm("mov.b64 {%0, %1}, %2;" : "=f"(r.x), "=f"(r.y) : "l"(a));
    return r;
}
__device__ __forceinline__ float2 ffma2(float2 a, float2 b, float2 c) {
    unsigned long long r;
    asm("fma.rn.f32x2 %0, %1, %2, %3;"
        : "=l"(r) : "l"(f2u(a)), "l"(f2u(b)), "l"(f2u(c)));
    return u2f(r);
}
__device__ __forceinline__ float2 lo2(float4 v) { return make_float2(v.x, v.y); }
__device__ __forceinline__ float2 hi2(float4 v) { return make_float2(v.z, v.w); }

__global__ __launch_bounds__(256, 2)
void rel_attn_kernel(const float* __restrict__ q,
                     const float* __restrict__ k,
                     const float* __restrict__ v,
                     const float* __restrict__ rel,
                     const float* __restrict__ mask,
                     float* __restrict__ out) {
    extern __shared__ float sm[];
    float* s_s  = sm + S_OFF;     // [TI][HH][SROW] scores -> exp(p) unnormalized
    float* red1 = sm + RED1_OFF;  // [TI][HH][DKK]  phase-2a result
    float* red2 = sm + RED2_OFF;  // [2][TI][HH][DKK] phase-2b per-half partials
    float* invs = sm + INV_OFF;   // [TI*HH]

    const int bid  = blockIdx.x;
    const int b    = bid >> 7;          // 128 tiles per batch
    const int i0   = (bid & 127) * TI;
    const int tid  = threadIdx.x;
    const int warp = tid >> 5;
    const int lane = tid & 31;
    const int dd   = lane & 7;          // d-octet owned by this lane
    const int jj   = lane >> 3;         // which of 4 j's in a warp step

    const float2 z2 = make_float2(0.f, 0.f);

    // ================= Phase 1a: s = scale*(q.k), warp w owns head h=w ======
    {
        const int h = warp;
        float4 qa[TI], qb[TI];
#pragma unroll
        for (int ti = 0; ti < TI; ti++) {
            const float* qp = q + ((size_t)(b * HH + h) * NN + (i0 + ti)) * DKK + dd * 8;
            qa[ti] = *(const float4*)qp;
            qb[ti] = *(const float4*)(qp + 4);
        }
        const float* kbase = k + ((size_t)(b * HH + h) * NN) * DKK + dd * 8;
#pragma unroll 2
        for (int s = 0; s < NN / 4; s++) {
            const int j = s * 4 + jj;
            const float* kp = kbase + (size_t)j * DKK;
            const float4 ka = *(const float4*)kp;
            const float4 kb = *(const float4*)(kp + 4);
#pragma unroll
            for (int ti = 0; ti < TI; ti++) {
                float2 a = ffma2(lo2(qa[ti]), lo2(ka), z2);
                a = ffma2(hi2(qa[ti]), hi2(ka), a);
                a = ffma2(lo2(qb[ti]), lo2(kb), a);
                a = ffma2(hi2(qb[ti]), hi2(kb), a);
                float r = a.x + a.y;
                r += __shfl_xor_sync(0xffffffffu, r, 1);
                r += __shfl_xor_sync(0xffffffffu, r, 2);
                r += __shfl_xor_sync(0xffffffffu, r, 4);
                if (dd == 0) s_s[(ti * HH + h) * SROW + j] = r * SCALE;
            }
        }
    }
    __syncthreads();

    // ================= Phase 1b: s += q.rel, warp = (ti, j-half) ============
    {
        const int ti    = warp & 3;
        const int jbase = (warp >> 2) * (NN / 2);
        float4 qa[HH], qb[HH];
#pragma unroll
        for (int h = 0; h < HH; h++) {
            const float* qp = q + ((size_t)(b * HH + h) * NN + (i0 + ti)) * DKK + dd * 8;
            qa[h] = *(const float4*)qp;
            qb[h] = *(const float4*)(qp + 4);
        }
        const float* rbase = rel + (((size_t)b * NN + (i0 + ti)) * NN) * DKK + dd * 8;
#pragma unroll 2
        for (int s = 0; s < NN / 8; s++) {
            const int j = jbase + s * 4 + jj;
            const float* rp = rbase + (size_t)j * DKK;
            const float4 ra = *(const float4*)rp;
            const float4 rb = *(const float4*)(rp + 4);
            float myr = 0.f;
#pragma unroll
            for (int h = 0; h < HH; h++) {
                float2 a = ffma2(lo2(qa[h]), lo2(ra), z2);
                a = ffma2(hi2(qa[h]), hi2(ra), a);
                a = ffma2(lo2(qb[h]), lo2(rb), a);
                a = ffma2(hi2(qb[h]), hi2(rb), a);
                float r = a.x + a.y;
                r += __shfl_xor_sync(0xffffffffu, r, 1);
                r += __shfl_xor_sync(0xffffffffu, r, 2);
                r += __shfl_xor_sync(0xffffffffu, r, 4);
                if (dd == h) myr = r;       // lane dd handles head h=dd
            }
            s_s[(ti * HH + dd) * SROW + j] += myr;  // conflict-free (SROW=516)
        }
    }
    __syncthreads();

    // ================= Softmax: 32 (ti,h) rows, 4 per warp ==================
    for (int row = warp; row < TI * HH; row += 8) {
        const int ti = row >> 3;
        const int h  = row & 7;
        const float* mp = mask + (((size_t)b * HH + h) * NN + (i0 + ti)) * NN;
        float* srow = s_s + row * SROW;
        float vals[16];
        float mx = -3.4e38f;
#pragma unroll
        for (int t = 0; t < 16; t++) {
            const int j = t * 32 + lane;
            float x = srow[j] + mp[j];
            vals[t] = x;
            mx = fmaxf(mx, x);
        }
#pragma unroll
        for (int o = 16; o > 0; o >>= 1)
            mx = fmaxf(mx, __shfl_xor_sync(0xffffffffu, mx, o));
        float sum = 0.f;
#pragma unroll
        for (int t = 0; t < 16; t++) {
            float e = __expf(vals[t] - mx);
            sum += e;
            srow[t * 32 + lane] = e;     // unnormalized p
        }
#pragma unroll
        for (int o = 16; o > 0; o >>= 1)
            sum += __shfl_xor_sync(0xffffffffu, sum, o);
        if (lane == 0) invs[row] = 1.0f / sum;
    }
    __syncthreads();

    // ================= Phase 2a: out1 = p.v, warp w owns head h=w ===========
    {
        const int h = warp;
        float2 acc[TI][4];
#pragma unroll
        for (int ti = 0; ti < TI; ti++)
#pragma unroll
            for (int c = 0; c < 4; c++) acc[ti][c] = z2;

        const float* vbase = v + ((size_t)(b * HH + h) * NN) * DKK + dd * 8;
#pragma unroll 2
        for (int s = 0; s < NN / 4; s++) {
            const int j = s * 4 + jj;
            const float* vp = vbase + (size_t)j * DKK;
            const float4 va = *(const float4*)vp;
            const float4 vb = *(const float4*)(vp + 4);
#pragma unroll
            for (int ti = 0; ti < TI; ti++) {
                const float p = s_s[(ti * HH + h) * SROW + j];
                const float2 p2 = make_float2(p, p);
                acc[ti][0] = ffma2(p2, lo2(va), acc[ti][0]);
                acc[ti][1] = ffma2(p2, hi2(va), acc[ti][1]);
                acc[ti][2] = ffma2(p2, lo2(vb), acc[ti][2]);
                acc[ti][3] = ffma2(p2, hi2(vb), acc[ti][3]);
            }
        }
        // reduce across jj groups (lanes dd, dd+8, dd+16, dd+24)
#pragma unroll
        for (int ti = 0; ti < TI; ti++)
#pragma unroll
            for (int c = 0; c < 4; c++) {
                acc[ti][c].x += __shfl_xor_sync(0xffffffffu, acc[ti][c].x, 8);
                acc[ti][c].x += __shfl_xor_sync(0xffffffffu, acc[ti][c].x, 16);
                acc[ti][c].y += __shfl_xor_sync(0xffffffffu, acc[ti][c].y, 8);
                acc[ti][c].y += __shfl_xor_sync(0xffffffffu, acc[ti][c].y, 16);
            }
        if (jj == 0) {
#pragma unroll
            for (int ti = 0; ti < TI; ti++) {
                float* rp = red1 + (ti * HH + h) * DKK + dd * 8;
                *(float4*)rp       = make_float4(acc[ti][0].x, acc[ti][0].y,
                                                 acc[ti][1].x, acc[ti][1].y);
                *(float4*)(rp + 4) = make_float4(acc[ti][2].x, acc[ti][2].y,
                                                 acc[ti][3].x, acc[ti][3].y);
            }
        }
    }

    // ================= Phase 2b: out2 = p.rel, warp = (ti, j-half) ==========
    {
        const int ti    = warp & 3;
        const int half  = warp >> 2;
        const int jbase = half * (NN / 2);
        float2 acc[HH][4];
#pragma unroll
        for (int h = 0; h < HH; h++)
#pragma unroll
            for (int c = 0; c < 4; c++) acc[h][c] = z2;

        const float* rbase = rel + (((size_t)b * NN + (i0 + ti)) * NN) * DKK + dd * 8;
#pragma unroll 2
        for (int s = 0; s < NN / 8; s++) {
            const int j = jbase + s * 4 + jj;
            const float* rp = rbase + (size_t)j * DKK;
            const float4 ra = *(const float4*)rp;
            const float4 rb = *(const float4*)(rp + 4);
#pragma unroll
            for (int h = 0; h < HH; h++) {
                const float p = s_s[(ti * HH + h) * SROW + j];
                const float2 p2 = make_float2(p, p);
                acc[h][0] = ffma2(p2, lo2(ra), acc[h][0]);
                acc[h][1] = ffma2(p2, hi2(ra), acc[h][1]);
                acc[h][2] = ffma2(p2, lo2(rb), acc[h][2]);
                acc[h][3] = ffma2(p2, hi2(rb), acc[h][3]);
            }
        }
#pragma unroll
        for (int h = 0; h < HH; h++)
#pragma unroll
            for (int c = 0; c < 4; c++) {
                acc[h][c].x += __shfl_xor_sync(0xffffffffu, acc[h][c].x, 8);
                acc[h][c].x += __shfl_xor_sync(0xffffffffu, acc[h][c].x, 16);
                acc[h][c].y += __shfl_xor_sync(0xffffffffu, acc[h][c].y, 8);
                acc[h][c].y += __shfl_xor_sync(0xffffffffu, acc[h][c].y, 16);
            }
        if (jj == 0) {
#pragma unroll
            for (int h = 0; h < HH; h++) {
                float* rp = red2 + ((size_t)half * TI * HH * DKK) +
                            (ti * HH + h) * DKK + dd * 8;
                *(float4*)rp       = make_float4(acc[h][0].x, acc[h][0].y,
                                                 acc[h][1].x, acc[h][1].y);
                *(float4*)(rp + 4) = make_float4(acc[h][2].x, acc[h][2].y,
                                                 acc[h][3].x, acc[h][3].y);
            }
        }
    }
    __syncthreads();

    // ================= Combine + normalize + store ==========================
    for (int idx = tid; idx < TI * HH * DKK; idx += 256) {
        const int ti = idx >> 9;           // /512
        const int rest = idx & 511;
        const int h  = rest >> 6;
        const int d  = rest & 63;
        float o = red1[idx] + red2[idx] + red2[TI * HH * DKK + idx];
        out[((size_t)(b * HH + h) * NN + (i0 + ti)) * DKK + d] = o * invs[ti * HH + h];
    }
}

extern "C" void kernel_launch(void* const* d_in, const int* in_sizes, int n_in,
                              void* d_out, int out_size) {
    const float* q    = (const float*)d_in[0];
    const float* k    = (const float*)d_in[1];
    const float* v    = (const float*)d_in[2];
    const float* rel  = (const float*)d_in[3];
    const float* mask = (const float*)d_in[4];
    float* out = (float*)d_out;

    cudaFuncSetAttribute(rel_attn_kernel,
                         cudaFuncAttributeMaxDynamicSharedMemorySize, SMEM_BYTES);
    rel_attn_kernel<<<BB * (NN / TI), 256, SMEM_BYTES>>>(q, k, v, rel, mask, out);
}

// round 4
// speedup vs baseline: 2.5755x; 1.2198x over previous
#include <cuda_runtime.h>
#include <cuda_bf16.h>
#include <math.h>

// Shapes fixed for this bench: B=4, H=8, N=512, DK=64
#define BB 4
#define HH 8
#define NN 512
#define DKK 64
#define TI 4                 // i-rows per CTA
#define SCALE 0.125f         // 1/sqrt(64)
#define SROW 516             // padded score row
#define TIBLK (HH*SROW + 4)  // per-ti block pad: ti stride = 4 banks

// smem layout in floats
#define S_OFF    0
#define RED1_OFF (TI*TIBLK)                   // 16528
#define RED2_OFF (RED1_OFF + TI*HH*DKK)       // 18576
#define INV_OFF  (RED2_OFF + 2*TI*HH*DKK)     // 22672
#define SMEM_FLOATS (INV_OFF + TI*HH)         // 22704
#define SMEM_BYTES (SMEM_FLOATS * 4)          // 90816

// ---------------- packed f32x2 helpers (FFMA2 on sm_103a) ----------------
__device__ __forceinline__ unsigned long long f2u(float2 a) {
    unsigned long long r;
    asm("mov.b64 %0, {%1, %2};" : "=l"(r) : "f"(a.x), "f"(a.y));
    return r;
}
__device__ __forceinline__ float2 u2f(unsigned long long a) {
    float2 r;
    asm("mov.b64 {%0, %1}, %2;" : "=f"(r.x), "=f"(r.y) : "l"(a));
    return r;
}
__device__ __forceinline__ float2 ffma2(float2 a, float2 b, float2 c) {
    unsigned long long r;
    asm("fma.rn.f32x2 %0, %1, %2, %3;"
        : "=l"(r) : "l"(f2u(a)), "l"(f2u(b)), "l"(f2u(c)));
    return u2f(r);
}
__device__ __forceinline__ float2 lo2(float4 v) { return make_float2(v.x, v.y); }
__device__ __forceinline__ float2 hi2(float4 v) { return make_float2(v.z, v.w); }

__global__ __launch_bounds__(256, 2)
void rel_attn_kernel(const float* __restrict__ q,
                     const float* __restrict__ k,
                     const float* __restrict__ v,
                     const float* __restrict__ rel,
                     const float* __restrict__ mask,
                     float* __restrict__ out) {
    extern __shared__ float sm[];
    float* s_s  = sm + S_OFF;     // [TI]{[HH][SROW]+4} scores -> unnormalized p
    float* red1 = sm + RED1_OFF;  // [TI][HH][DKK]  phase-2a result
    float* red2 = sm + RED2_OFF;  // [2][TI][HH][DKK] phase-2b per-half partials
    float* invs = sm + INV_OFF;   // [TI*HH]

    const int bid  = blockIdx.x;
    const int b    = bid >> 7;
    const int i0   = (bid & 127) * TI;
    const int tid  = threadIdx.x;
    const int warp = tid >> 5;
    const int lane = tid & 31;
    const int dd   = lane & 7;          // d-octet owned by this lane
    const int jj   = lane >> 3;         // which of 4 j's in a warp step
    const bool b0  = (dd & 1) != 0;
    const bool b1  = (dd & 2) != 0;
    const bool b2  = (dd & 4) != 0;

    const float2 z2 = make_float2(0.f, 0.f);

    // ===== Phase 1a: s = scale*(q.k), warp w owns head h=w =================
    {
        const int h = warp;
        float4 qa[TI], qb[TI];
#pragma unroll
        for (int ti = 0; ti < TI; ti++) {
            const float* qp = q + ((size_t)(b * HH + h) * NN + (i0 + ti)) * DKK + dd * 8;
            qa[ti] = *(const float4*)qp;
            qb[ti] = *(const float4*)(qp + 4);
        }
        const float* kbase = k + ((size_t)(b * HH + h) * NN) * DKK + dd * 8;
#pragma unroll 4
        for (int s = 0; s < NN / 4; s++) {
            const int j = s * 4 + jj;
            const float* kp = kbase + (size_t)j * DKK;
            const float4 ka = *(const float4*)kp;
            const float4 kb = *(const float4*)(kp + 4);
            float r[TI];
#pragma unroll
            for (int ti = 0; ti < TI; ti++) {
                float2 a = ffma2(lo2(qa[ti]), lo2(ka), z2);
                a = ffma2(hi2(qa[ti]), hi2(ka), a);
                a = ffma2(lo2(qb[ti]), lo2(kb), a);
                a = ffma2(hi2(qb[ti]), hi2(kb), a);
                r[ti] = a.x + a.y;
            }
            // butterfly: reduce 4 values over 8 dd-lanes; lane dd ends with S[dd&3]
            // round 1 (xor 2): keep t in {2*b1, 2*b1+1}
            float k0 = b1 ? r[2] : r[0];
            float k1 = b1 ? r[3] : r[1];
            float o0 = b1 ? r[0] : r[2];
            float o1 = b1 ? r[1] : r[3];
            k0 += __shfl_xor_sync(0xffffffffu, o0, 2);
            k1 += __shfl_xor_sync(0xffffffffu, o1, 2);
            // round 2 (xor 1): keep t = 2*b1 + b0
            float kk = b0 ? k1 : k0;
            float oo = b0 ? k0 : k1;
            kk += __shfl_xor_sync(0xffffffffu, oo, 1);
            // round 3 (xor 4): fold remaining lane pair
            kk += __shfl_xor_sync(0xffffffffu, kk, 4);
            if (dd < 4) s_s[dd * TIBLK + h * SROW + j] = kk * SCALE;
        }
    }
    __syncthreads();

    // ===== Phase 1b: s += q.rel, warp = (ti, j-half) ========================
    {
        const int ti    = warp & 3;
        const int jbase = (warp >> 2) * (NN / 2);
        float4 qa[HH], qb[HH];
#pragma unroll
        for (int h = 0; h < HH; h++) {
            const float* qp = q + ((size_t)(b * HH + h) * NN + (i0 + ti)) * DKK + dd * 8;
            qa[h] = *(const float4*)qp;
            qb[h] = *(const float4*)(qp + 4);
        }
        const float* rbase = rel + (((size_t)b * NN + (i0 + ti)) * NN) * DKK + dd * 8;
#pragma unroll 2
        for (int s = 0; s < NN / 8; s++) {
            const int j = jbase + s * 4 + jj;
            const float* rp = rbase + (size_t)j * DKK;
            const float4 ra = *(const float4*)rp;
            const float4 rb = *(const float4*)(rp + 4);
            float r[HH];
#pragma unroll
            for (int h = 0; h < HH; h++) {
                float2 a = ffma2(lo2(qa[h]), lo2(ra), z2);
                a = ffma2(hi2(qa[h]), hi2(ra), a);
                a = ffma2(lo2(qb[h]), lo2(rb), a);
                a = ffma2(hi2(qb[h]), hi2(rb), a);
                r[h] = a.x + a.y;
            }
            // butterfly: reduce 8 values over 8 dd-lanes; lane dd ends with S[dd]
            // round 1 (xor 4): keep h with bit2 == b2
            float c0 = b2 ? r[4] : r[0];
            float c1 = b2 ? r[5] : r[1];
            float c2 = b2 ? r[6] : r[2];
            float c3 = b2 ? r[7] : r[3];
            float d0 = b2 ? r[0] : r[4];
            float d1 = b2 ? r[1] : r[5];
            float d2 = b2 ? r[2] : r[6];
            float d3 = b2 ? r[3] : r[7];
            c0 += __shfl_xor_sync(0xffffffffu, d0, 4);
            c1 += __shfl_xor_sync(0xffffffffu, d1, 4);
            c2 += __shfl_xor_sync(0xffffffffu, d2, 4);
            c3 += __shfl_xor_sync(0xffffffffu, d3, 4);
            // round 2 (xor 2): keep bit1 == b1
            float e0 = b1 ? c2 : c0;
            float e1 = b1 ? c3 : c1;
            float f0 = b1 ? c0 : c2;
            float f1 = b1 ? c1 : c3;
            e0 += __shfl_xor_sync(0xffffffffu, f0, 2);
            e1 += __shfl_xor_sync(0xffffffffu, f1, 2);
            // round 3 (xor 1): keep bit0 == b0
            float w = b0 ? e1 : e0;
            float o = b0 ? e0 : e1;
            w += __shfl_xor_sync(0xffffffffu, o, 1);
            s_s[ti * TIBLK + dd * SROW + j] += w;   // conflict-free scatter
        }
    }
    __syncthreads();

    // ===== Softmax: 32 (ti,h) rows, 4 per warp ==============================
    for (int row = warp; row < TI * HH; row += 8) {
        const int ti = row >> 3;
        const int h  = row & 7;
        const float* mp = mask + (((size_t)b * HH + h) * NN + (i0 + ti)) * NN;
        float* srow = s_s + ti * TIBLK + h * SROW;
        float vals[16];
        float mx = -3.4e38f;
#pragma unroll
        for (int t = 0; t < 16; t++) {
            const int j = t * 32 + lane;
            float x = srow[j] + mp[j];
            vals[t] = x;
            mx = fmaxf(mx, x);
        }
#pragma unroll
        for (int o = 16; o > 0; o >>= 1)
            mx = fmaxf(mx, __shfl_xor_sync(0xffffffffu, mx, o));
        float sum = 0.f;
#pragma unroll
        for (int t = 0; t < 16; t++) {
            float e = __expf(vals[t] - mx);
            sum += e;
            srow[t * 32 + lane] = e;     // unnormalized p
        }
#pragma unroll
        for (int o = 16; o > 0; o >>= 1)
            sum += __shfl_xor_sync(0xffffffffu, sum, o);
        if (lane == 0) invs[row] = 1.0f / sum;
    }
    __syncthreads();

    // ===== Phase 2a: out1 = p.v, warp w owns head h=w =======================
    {
        const int h = warp;
        float2 acc[TI][4];
#pragma unroll
        for (int ti = 0; ti < TI; ti++)
#pragma unroll
            for (int c = 0; c < 4; c++) acc[ti][c] = z2;

        const float* vbase = v + ((size_t)(b * HH + h) * NN) * DKK + dd * 8;
#pragma unroll 2
        for (int s = 0; s < NN / 4; s++) {
            const int j = s * 4 + jj;
            const float* vp = vbase + (size_t)j * DKK;
            const float4 va = *(const float4*)vp;
            const float4 vb = *(const float4*)(vp + 4);
#pragma unroll
            for (int ti = 0; ti < TI; ti++) {
                const float p = s_s[ti * TIBLK + h * SROW + j];
                const float2 p2 = make_float2(p, p);
                acc[ti][0] = ffma2(p2, lo2(va), acc[ti][0]);
                acc[ti][1] = ffma2(p2, hi2(va), acc[ti][1]);
                acc[ti][2] = ffma2(p2, lo2(vb), acc[ti][2]);
                acc[ti][3] = ffma2(p2, hi2(vb), acc[ti][3]);
            }
        }
#pragma unroll
        for (int ti = 0; ti < TI; ti++)
#pragma unroll
            for (int c = 0; c < 4; c++) {
                acc[ti][c].x += __shfl_xor_sync(0xffffffffu, acc[ti][c].x, 8);
                acc[ti][c].x += __shfl_xor_sync(0xffffffffu, acc[ti][c].x, 16);
                acc[ti][c].y += __shfl_xor_sync(0xffffffffu, acc[ti][c].y, 8);
                acc[ti][c].y += __shfl_xor_sync(0xffffffffu, acc[ti][c].y, 16);
            }
        if (jj == 0) {
#pragma unroll
            for (int ti = 0; ti < TI; ti++) {
                float* rp = red1 + (ti * HH + h) * DKK + dd * 8;
                *(float4*)rp       = make_float4(acc[ti][0].x, acc[ti][0].y,
                                                 acc[ti][1].x, acc[ti][1].y);
                *(float4*)(rp + 4) = make_float4(acc[ti][2].x, acc[ti][2].y,
                                                 acc[ti][3].x, acc[ti][3].y);
            }
        }
    }

    // ===== Phase 2b: out2 = p.rel, warp = (ti, j-half), j DESCENDING ========
    // (reversed order: rel rows most recently loaded in 1b are re-read first,
    //  maximizing L2 hits on the second rel pass)
    {
        const int ti    = warp & 3;
        const int half  = warp >> 2;
        const int jbase = half * (NN / 2);
        float2 acc[HH][4];
#pragma unroll
        for (int h = 0; h < HH; h++)
#pragma unroll
            for (int c = 0; c < 4; c++) acc[h][c] = z2;

        const float* rbase = rel + (((size_t)b * NN + (i0 + ti)) * NN) * DKK + dd * 8;
#pragma unroll 2
        for (int s = NN / 8 - 1; s >= 0; s--) {
            const int j = jbase + s * 4 + jj;
            const float* rp = rbase + (size_t)j * DKK;
            const float4 ra = *(const float4*)rp;
            const float4 rb = *(const float4*)(rp + 4);
#pragma unroll
            for (int h = 0; h < HH; h++) {
                const float p = s_s[ti * TIBLK + h * SROW + j];
                const float2 p2 = make_float2(p, p);
                acc[h][0] = ffma2(p2, lo2(ra), acc[h][0]);
                acc[h][1] = ffma2(p2, hi2(ra), acc[h][1]);
                acc[h][2] = ffma2(p2, lo2(rb), acc[h][2]);
                acc[h][3] = ffma2(p2, hi2(rb), acc[h][3]);
            }
        }
#pragma unroll
        for (int h = 0; h < HH; h++)
#pragma unroll
            for (int c = 0; c < 4; c++) {
                acc[h][c].x += __shfl_xor_sync(0xffffffffu, acc[h][c].x, 8);
                acc[h][c].x += __shfl_xor_sync(0xffffffffu, acc[h][c].x, 16);
                acc[h][c].y += __shfl_xor_sync(0xffffffffu, acc[h][c].y, 8);
                acc[h][c].y += __shfl_xor_sync(0xffffffffu, acc[h][c].y, 16);
            }
        if (jj == 0) {
#pragma unroll
            for (int h = 0; h < HH; h++) {
                float* rp = red2 + ((size_t)half * TI * HH * DKK) +
                            (ti * HH + h) * DKK + dd * 8;
                *(float4*)rp       = make_float4(acc[h][0].x, acc[h][0].y,
                                                 acc[h][1].x, acc[h][1].y);
                *(float4*)(rp + 4) = make_float4(acc[h][2].x, acc[h][2].y,
                                                 acc[h][3].x, acc[h][3].y);
            }
        }
    }
    __syncthreads();

    // ===== Combine + normalize + store ======================================
    for (int idx = tid; idx < TI * HH * DKK; idx += 256) {
        const int ti = idx >> 9;
        const int rest = idx & 511;
        const int h  = rest >> 6;
        const int d  = rest & 63;
        float o = red1[idx] + red2[idx] + red2[TI * HH * DKK + idx];
        out[((size_t)(b * HH + h) * NN + (i0 + ti)) * DKK + d] = o * invs[ti * HH + h];
    }
}

extern "C" void kernel_launch(void* const* d_in, const int* in_sizes, int n_in,
                              void* d_out, int out_size) {
    const float* q    = (const float*)d_in[0];
    const float* k    = (const float*)d_in[1];
    const float* v    = (const float*)d_in[2];
    const float* rel  = (const float*)d_in[3];
    const float* mask = (const float*)d_in[4];
    float* out = (float*)d_out;

    cudaFuncSetAttribute(rel_attn_kernel,
                         cudaFuncAttributeMaxDynamicSharedMemorySize, SMEM_BYTES);
    rel_attn_kernel<<<BB * (NN / TI), 256, SMEM_BYTES>>>(q, k, v, rel, mask, out);
}

// round 5
// speedup vs baseline: 2.6279x; 1.0203x over previous
#include <cuda_runtime.h>
#include <cuda_bf16.h>
#include <math.h>

// Shapes fixed for this bench: B=4, H=8, N=512, DK=64
#define BB 4
#define HH 8
#define NN 512
#define DKK 64
#define TI 4                 // i-rows per CTA
#define SCALE 0.125f         // 1/sqrt(64)
#define SROW 516             // padded score row
#define TIBLK (HH*SROW + 4)  // per-ti block pad

// smem layout in floats
#define S_OFF    0
#define RED1_OFF (TI*TIBLK)                   // 16528
#define RED2_OFF (RED1_OFF + TI*HH*DKK)       // 18576
#define INV_OFF  (RED2_OFF + 2*TI*HH*DKK)     // 22672
#define SMEM_FLOATS (INV_OFF + TI*HH)         // 22704
#define SMEM_BYTES (SMEM_FLOATS * 4)          // 90816

// ---------------- packed f32x2 helpers (FFMA2 on sm_103a) ----------------
__device__ __forceinline__ unsigned long long f2u(float2 a) {
    unsigned long long r;
    asm("mov.b64 %0, {%1, %2};" : "=l"(r) : "f"(a.x), "f"(a.y));
    return r;
}
__device__ __forceinline__ float2 u2f(unsigned long long a) {
    float2 r;
    asm("mov.b64 {%0, %1}, %2;" : "=f"(r.x), "=f"(r.y) : "l"(a));
    return r;
}
__device__ __forceinline__ float2 ffma2(float2 a, float2 b, float2 c) {
    unsigned long long r;
    asm("fma.rn.f32x2 %0, %1, %2, %3;"
        : "=l"(r) : "l"(f2u(a)), "l"(f2u(b)), "l"(f2u(c)));
    return u2f(r);
}
__device__ __forceinline__ float2 lo2(float4 v) { return make_float2(v.x, v.y); }
__device__ __forceinline__ float2 hi2(float4 v) { return make_float2(v.z, v.w); }

__global__ __launch_bounds__(256, 2)
void rel_attn_kernel(const float* __restrict__ q,
                     const float* __restrict__ k,
                     const float* __restrict__ v,
                     const float* __restrict__ rel,
                     const float* __restrict__ mask,
                     float* __restrict__ out) {
    extern __shared__ float sm[];
    float* s_s  = sm + S_OFF;     // [TI]{[HH][SROW]+4} scores -> unnormalized p
    float* red1 = sm + RED1_OFF;  // [TI][HH][DKK]  p.v result
    float* red2 = sm + RED2_OFF;  // [2][TI][HH][DKK] p.rel per-half partials
    float* invs = sm + INV_OFF;   // [TI*HH]

    const int bid  = blockIdx.x;
    const int b    = bid >> 7;
    const int i0   = (bid & 127) * TI;
    const int tid  = threadIdx.x;
    const int warp = tid >> 5;
    const int lane = tid & 31;
    const int dd   = lane & 7;          // d-octet owned by this lane
    const int jj   = lane >> 3;         // which of 4 j's in a warp step
    const bool b0  = (dd & 1) != 0;
    const bool b1  = (dd & 2) != 0;
    const bool b2  = (dd & 4) != 0;

    const float2 z2 = make_float2(0.f, 0.f);

    // ===== Phase 1a: s = (scale*q).k, warp w owns head h=w =================
    {
        const int h = warp;
        float4 qa[TI], qb[TI];
#pragma unroll
        for (int ti = 0; ti < TI; ti++) {
            const float* qp = q + ((size_t)(b * HH + h) * NN + (i0 + ti)) * DKK + dd * 8;
            float4 a = *(const float4*)qp;
            float4 c = *(const float4*)(qp + 4);
            a.x *= SCALE; a.y *= SCALE; a.z *= SCALE; a.w *= SCALE;
            c.x *= SCALE; c.y *= SCALE; c.z *= SCALE; c.w *= SCALE;
            qa[ti] = a; qb[ti] = c;
        }
        const float* kbase = k + ((size_t)(b * HH + h) * NN) * DKK + dd * 8;
#pragma unroll 4
        for (int s = 0; s < NN / 4; s++) {
            const int j = s * 4 + jj;
            const float* kp = kbase + (size_t)j * DKK;
            const float4 ka = *(const float4*)kp;
            const float4 kb = *(const float4*)(kp + 4);
            float r[TI];
#pragma unroll
            for (int ti = 0; ti < TI; ti++) {
                float2 a = ffma2(lo2(qa[ti]), lo2(ka), z2);
                a = ffma2(hi2(qa[ti]), hi2(ka), a);
                a = ffma2(lo2(qb[ti]), lo2(kb), a);
                a = ffma2(hi2(qb[ti]), hi2(kb), a);
                r[ti] = a.x + a.y;
            }
            // butterfly: 4 values over 8 dd-lanes; lane dd ends with S[dd&3]
            float k0 = b1 ? r[2] : r[0];
            float k1 = b1 ? r[3] : r[1];
            float o0 = b1 ? r[0] : r[2];
            float o1 = b1 ? r[1] : r[3];
            k0 += __shfl_xor_sync(0xffffffffu, o0, 2);
            k1 += __shfl_xor_sync(0xffffffffu, o1, 2);
            float kk = b0 ? k1 : k0;
            float oo = b0 ? k0 : k1;
            kk += __shfl_xor_sync(0xffffffffu, oo, 1);
            kk += __shfl_xor_sync(0xffffffffu, kk, 4);
            if (dd < 4) s_s[dd * TIBLK + h * SROW + j] = kk;
        }
    }
    __syncthreads();

    // ===== Phase 1b: s += q.rel, warp = (ti, j-half), j ascending ===========
    {
        const int ti    = warp & 3;
        const int jbase = (warp >> 2) * (NN / 2);
        float4 qa[HH], qb[HH];
#pragma unroll
        for (int h = 0; h < HH; h++) {
            const float* qp = q + ((size_t)(b * HH + h) * NN + (i0 + ti)) * DKK + dd * 8;
            qa[h] = *(const float4*)qp;
            qb[h] = *(const float4*)(qp + 4);
        }
        const float* rbase = rel + (((size_t)b * NN + (i0 + ti)) * NN) * DKK + dd * 8;
#pragma unroll 2
        for (int s = 0; s < NN / 8; s++) {
            const int j = jbase + s * 4 + jj;
            const float* rp = rbase + (size_t)j * DKK;
            const float4 ra = *(const float4*)rp;
            const float4 rb = *(const float4*)(rp + 4);
            float r[HH];
#pragma unroll
            for (int h = 0; h < HH; h++) {
                float2 a = ffma2(lo2(qa[h]), lo2(ra), z2);
                a = ffma2(hi2(qa[h]), hi2(ra), a);
                a = ffma2(lo2(qb[h]), lo2(rb), a);
                a = ffma2(hi2(qb[h]), hi2(rb), a);
                r[h] = a.x + a.y;
            }
            // butterfly: 8 values over 8 dd-lanes; lane dd ends with S[dd]
            float c0 = b2 ? r[4] : r[0];
            float c1 = b2 ? r[5] : r[1];
            float c2 = b2 ? r[6] : r[2];
            float c3 = b2 ? r[7] : r[3];
            float d0 = b2 ? r[0] : r[4];
            float d1 = b2 ? r[1] : r[5];
            float d2 = b2 ? r[2] : r[6];
            float d3 = b2 ? r[3] : r[7];
            c0 += __shfl_xor_sync(0xffffffffu, d0, 4);
            c1 += __shfl_xor_sync(0xffffffffu, d1, 4);
            c2 += __shfl_xor_sync(0xffffffffu, d2, 4);
            c3 += __shfl_xor_sync(0xffffffffu, d3, 4);
            float e0 = b1 ? c2 : c0;
            float e1 = b1 ? c3 : c1;
            float f0 = b1 ? c0 : c2;
            float f1 = b1 ? c1 : c3;
            e0 += __shfl_xor_sync(0xffffffffu, f0, 2);
            e1 += __shfl_xor_sync(0xffffffffu, f1, 2);
            float w = b0 ? e1 : e0;
            float o = b0 ? e0 : e1;
            w += __shfl_xor_sync(0xffffffffu, o, 1);
            s_s[ti * TIBLK + dd * SROW + j] += w;   // conflict-free scatter
        }
    }
    __syncthreads();

    // ===== Softmax: 32 (ti,h) rows, 4 per warp, float4-vectorized ===========
    for (int row = warp; row < TI * HH; row += 8) {
        const int ti = row >> 3;
        const int h  = row & 7;
        const float4* mp4 = (const float4*)(mask +
                            (((size_t)b * HH + h) * NN + (i0 + ti)) * NN);
        float4* sr4 = (float4*)(s_s + ti * TIBLK + h * SROW);
        float4 vals[4];
        float mx = -3.4e38f;
#pragma unroll
        for (int t = 0; t < 4; t++) {
            const int j4 = t * 32 + lane;
            float4 x = sr4[j4];
            const float4 m = mp4[j4];
            x.x += m.x; x.y += m.y; x.z += m.z; x.w += m.w;
            vals[t] = x;
            mx = fmaxf(mx, fmaxf(fmaxf(x.x, x.y), fmaxf(x.z, x.w)));
        }
#pragma unroll
        for (int o = 16; o > 0; o >>= 1)
            mx = fmaxf(mx, __shfl_xor_sync(0xffffffffu, mx, o));
        float sum = 0.f;
#pragma unroll
        for (int t = 0; t < 4; t++) {
            float4 e;
            e.x = __expf(vals[t].x - mx);
            e.y = __expf(vals[t].y - mx);
            e.z = __expf(vals[t].z - mx);
            e.w = __expf(vals[t].w - mx);
            sum += (e.x + e.y) + (e.z + e.w);
            sr4[t * 32 + lane] = e;      // unnormalized p
        }
#pragma unroll
        for (int o = 16; o > 0; o >>= 1)
            sum += __shfl_xor_sync(0xffffffffu, sum, o);
        if (lane == 0) invs[row] = 1.0f / sum;
    }
    __syncthreads();

    // ===== Phase 2b FIRST: out2 = p.rel, warp = (ti, j-half), j DESCENDING ==
    // Runs right after softmax so the rel tile read in 1b is still L2-resident
    // (descending order re-reads the most recently touched lines first).
    {
        const int ti    = warp & 3;
        const int half  = warp >> 2;
        const int jbase = half * (NN / 2);
        float2 acc[HH][4];
#pragma unroll
        for (int h = 0; h < HH; h++)
#pragma unroll
            for (int c = 0; c < 4; c++) acc[h][c] = z2;

        const float* rbase = rel + (((size_t)b * NN + (i0 + ti)) * NN) * DKK + dd * 8;
#pragma unroll 2
        for (int s = NN / 8 - 1; s >= 0; s--) {
            const int j = jbase + s * 4 + jj;
            const float* rp = rbase + (size_t)j * DKK;
            const float4 ra = *(const float4*)rp;
            const float4 rb = *(const float4*)(rp + 4);
#pragma unroll
            for (int h = 0; h < HH; h++) {
                const float p = s_s[ti * TIBLK + h * SROW + j];
                const float2 p2 = make_float2(p, p);
                acc[h][0] = ffma2(p2, lo2(ra), acc[h][0]);
                acc[h][1] = ffma2(p2, hi2(ra), acc[h][1]);
                acc[h][2] = ffma2(p2, lo2(rb), acc[h][2]);
                acc[h][3] = ffma2(p2, hi2(rb), acc[h][3]);
            }
        }
#pragma unroll
        for (int h = 0; h < HH; h++)
#pragma unroll
            for (int c = 0; c < 4; c++) {
                acc[h][c].x += __shfl_xor_sync(0xffffffffu, acc[h][c].x, 8);
                acc[h][c].x += __shfl_xor_sync(0xffffffffu, acc[h][c].x, 16);
                acc[h][c].y += __shfl_xor_sync(0xffffffffu, acc[h][c].y, 8);
                acc[h][c].y += __shfl_xor_sync(0xffffffffu, acc[h][c].y, 16);
            }
        if (jj == 0) {
#pragma unroll
            for (int h = 0; h < HH; h++) {
                float* rp = red2 + ((size_t)half * TI * HH * DKK) +
                            (ti * HH + h) * DKK + dd * 8;
                *(float4*)rp       = make_float4(acc[h][0].x, acc[h][0].y,
                                                 acc[h][1].x, acc[h][1].y);
                *(float4*)(rp + 4) = make_float4(acc[h][2].x, acc[h][2].y,
                                                 acc[h][3].x, acc[h][3].y);
            }
        }
    }

    // ===== Phase 2a: out1 = p.v, warp w owns head h=w =======================
    {
        const int h = warp;
        float2 acc[TI][4];
#pragma unroll
        for (int ti = 0; ti < TI; ti++)
#pragma unroll
            for (int c = 0; c < 4; c++) acc[ti][c] = z2;

        const float* vbase = v + ((size_t)(b * HH + h) * NN) * DKK + dd * 8;
#pragma unroll 2
        for (int s = 0; s < NN / 4; s++) {
            const int j = s * 4 + jj;
            const float* vp = vbase + (size_t)j * DKK;
            const float4 va = *(const float4*)vp;
            const float4 vb = *(const float4*)(vp + 4);
#pragma unroll
            for (int ti = 0; ti < TI; ti++) {
                const float p = s_s[ti * TIBLK + h * SROW + j];
                const float2 p2 = make_float2(p, p);
                acc[ti][0] = ffma2(p2, lo2(va), acc[ti][0]);
                acc[ti][1] = ffma2(p2, hi2(va), acc[ti][1]);
                acc[ti][2] = ffma2(p2, lo2(vb), acc[ti][2]);
                acc[ti][3] = ffma2(p2, hi2(vb), acc[ti][3]);
            }
        }
#pragma unroll
        for (int ti = 0; ti < TI; ti++)
#pragma unroll
            for (int c = 0; c < 4; c++) {
                acc[ti][c].x += __shfl_xor_sync(0xffffffffu, acc[ti][c].x, 8);
                acc[ti][c].x += __shfl_xor_sync(0xffffffffu, acc[ti][c].x, 16);
                acc[ti][c].y += __shfl_xor_sync(0xffffffffu, acc[ti][c].y, 8);
                acc[ti][c].y += __shfl_xor_sync(0xffffffffu, acc[ti][c].y, 16);
            }
        if (jj == 0) {
#pragma unroll
            for (int ti = 0; ti < TI; ti++) {
                float* rp = red1 + (ti * HH + h) * DKK + dd * 8;
                *(float4*)rp       = make_float4(acc[ti][0].x, acc[ti][0].y,
                                                 acc[ti][1].x, acc[ti][1].y);
                *(float4*)(rp + 4) = make_float4(acc[ti][2].x, acc[ti][2].y,
                                                 acc[ti][3].x, acc[ti][3].y);
            }
        }
    }
    __syncthreads();

    // ===== Combine + normalize + store (float4) =============================
    {
        const int Q = TI * HH * DKK / 4;            // 512 float4s
        const float4* r14 = (const float4*)red1;
        const float4* r24 = (const float4*)red2;
        for (int idx4 = tid; idx4 < Q; idx4 += 256) {
            const float4 a  = r14[idx4];
            const float4 b2_ = r24[idx4];
            const float4 c  = r24[Q + idx4];
            const int idx = idx4 << 2;
            const int ti = idx >> 9;
            const int h  = (idx >> 6) & 7;
            const int d  = idx & 63;
            const float s = invs[ti * HH + h];
            float4 o;
            o.x = (a.x + b2_.x + c.x) * s;
            o.y = (a.y + b2_.y + c.y) * s;
            o.z = (a.z + b2_.z + c.z) * s;
            o.w = (a.w + b2_.w + c.w) * s;
            *(float4*)&out[((size_t)(b * HH + h) * NN + (i0 + ti)) * DKK + d] = o;
        }
    }
}

extern "C" void kernel_launch(void* const* d_in, const int* in_sizes, int n_in,
                              void* d_out, int out_size) {
    const float* q    = (const float*)d_in[0];
    const float* k    = (const float*)d_in[1];
    const float* v    = (const float*)d_in[2];
    const float* rel  = (const float*)d_in[3];
    const float* mask = (const float*)d_in[4];
    float* out = (float*)d_out;

    cudaFuncSetAttribute(rel_attn_kernel,
                         cudaFuncAttributeMaxDynamicSharedMemorySize, SMEM_BYTES);
    rel_attn_kernel<<<BB * (NN / TI), 256, SMEM_BYTES>>>(q, k, v, rel, mask, out);
}

// round 6
// speedup vs baseline: 2.8823x; 1.0968x over previous
#include <cuda_runtime.h>
#include <cuda_bf16.h>
#include <math.h>

// Shapes fixed for this bench: B=4, H=8, N=512, DK=64
#define BB 4
#define HH 8
#define NN 512
#define DKK 64
#define TI 8                 // i-rows per CTA
#define NT 512               // threads per CTA (16 warps)
#define SCALE 0.125f         // 1/sqrt(64)
#define SROW 516             // padded score row (h stride: 516%32=4 banks)
#define TIBLK (HH*SROW + 4)  // 4132 (ti stride: 4132%32=4 banks)

// smem layout in floats
#define S_OFF    0
#define RED1_OFF (TI*TIBLK)                    // 33056
#define RED2_OFF (RED1_OFF + 2*TI*HH*DKK)      // 41248
#define INV_OFF  (RED2_OFF + 2*TI*HH*DKK)      // 49440
#define SMEM_FLOATS (INV_OFF + TI*HH)          // 49504
#define SMEM_BYTES (SMEM_FLOATS * 4)           // 198016 (<227KB)

// ---------------- packed f32x2 helpers (FFMA2 on sm_103a) ----------------
__device__ __forceinline__ unsigned long long f2u(float2 a) {
    unsigned long long r;
    asm("mov.b64 %0, {%1, %2};" : "=l"(r) : "f"(a.x), "f"(a.y));
    return r;
}
__device__ __forceinline__ float2 u2f(unsigned long long a) {
    float2 r;
    asm("mov.b64 {%0, %1}, %2;" : "=f"(r.x), "=f"(r.y) : "l"(a));
    return r;
}
__device__ __forceinline__ float2 ffma2(float2 a, float2 b, float2 c) {
    unsigned long long r;
    asm("fma.rn.f32x2 %0, %1, %2, %3;"
        : "=l"(r) : "l"(f2u(a)), "l"(f2u(b)), "l"(f2u(c)));
    return u2f(r);
}
__device__ __forceinline__ float2 lo2(float4 v) { return make_float2(v.x, v.y); }
__device__ __forceinline__ float2 hi2(float4 v) { return make_float2(v.z, v.w); }

// Reduce 8 per-lane values r[0..7] across the 8 dd-lanes (lane bits 0..2).
// Lane with dd==t returns the full sum of r[t] across those 8 lanes.
__device__ __forceinline__ float butterfly8(const float r[8],
                                            bool b0, bool b1, bool b2) {
    float c0 = b2 ? r[4] : r[0];
    float c1 = b2 ? r[5] : r[1];
    float c2 = b2 ? r[6] : r[2];
    float c3 = b2 ? r[7] : r[3];
    float d0 = b2 ? r[0] : r[4];
    float d1 = b2 ? r[1] : r[5];
    float d2 = b2 ? r[2] : r[6];
    float d3 = b2 ? r[3] : r[7];
    c0 += __shfl_xor_sync(0xffffffffu, d0, 4);
    c1 += __shfl_xor_sync(0xffffffffu, d1, 4);
    c2 += __shfl_xor_sync(0xffffffffu, d2, 4);
    c3 += __shfl_xor_sync(0xffffffffu, d3, 4);
    float e0 = b1 ? c2 : c0;
    float e1 = b1 ? c3 : c1;
    float f0 = b1 ? c0 : c2;
    float f1 = b1 ? c1 : c3;
    e0 += __shfl_xor_sync(0xffffffffu, f0, 2);
    e1 += __shfl_xor_sync(0xffffffffu, f1, 2);
    float w = b0 ? e1 : e0;
    float o = b0 ? e0 : e1;
    w += __shfl_xor_sync(0xffffffffu, o, 1);
    return w;
}

__global__ __launch_bounds__(NT, 1)
void rel_attn_kernel(const float* __restrict__ q,
                     const float* __restrict__ k,
                     const float* __restrict__ v,
                     const float* __restrict__ rel,
                     const float* __restrict__ mask,
                     float* __restrict__ out) {
    extern __shared__ float sm[];
    float* s_s  = sm + S_OFF;     // [TI]{[HH][SROW]} scores -> unnormalized p
    float* red1 = sm + RED1_OFF;  // [2][TI*HH][DKK] p.v per-jhalf partials
    float* red2 = sm + RED2_OFF;  // [2][TI*HH][DKK] p.rel per-jhalf partials
    float* invs = sm + INV_OFF;   // [TI*HH]

    const int bid  = blockIdx.x;
    const int b    = bid >> 6;           // 64 tiles per batch
    const int i0   = (bid & 63) * TI;
    const int tid  = threadIdx.x;
    const int warp = tid >> 5;
    const int lane = tid & 31;
    const int dd   = lane & 7;           // d-octet owned by this lane
    const int jj   = lane >> 3;          // which of 4 j's in a warp step
    const bool b0  = (dd & 1) != 0;
    const bool b1  = (dd & 2) != 0;
    const bool b2  = (dd & 4) != 0;

    const int sub  = warp & 7;           // head (1a/2a) or ti (1b/2b)
    const int jh   = warp >> 3;          // j-half owned by this warp
    const int jo   = jh * (NN / 2);

    const float2 z2 = make_float2(0.f, 0.f);

    // ===== Phase 1a: s = (scale*q).k ; warp=(h, jhalf) ======================
    {
        const int h = sub;
        float4 qa[TI], qb[TI];
#pragma unroll
        for (int ti = 0; ti < TI; ti++) {
            const float* qp = q + ((size_t)(b * HH + h) * NN + (i0 + ti)) * DKK + dd * 8;
            float4 a = *(const float4*)qp;
            float4 c = *(const float4*)(qp + 4);
            a.x *= SCALE; a.y *= SCALE; a.z *= SCALE; a.w *= SCALE;
            c.x *= SCALE; c.y *= SCALE; c.z *= SCALE; c.w *= SCALE;
            qa[ti] = a; qb[ti] = c;
        }
        const float* kbase = k + ((size_t)(b * HH + h) * NN) * DKK + dd * 8;
#pragma unroll 2
        for (int s = 0; s < NN / 8; s++) {
            const int j = jo + s * 4 + jj;
            const float* kp = kbase + (size_t)j * DKK;
            const float4 ka = *(const float4*)kp;
            const float4 kb = *(const float4*)(kp + 4);
            float r[TI];
#pragma unroll
            for (int ti = 0; ti < TI; ti++) {
                float2 a = ffma2(lo2(qa[ti]), lo2(ka), z2);
                a = ffma2(hi2(qa[ti]), hi2(ka), a);
                a = ffma2(lo2(qb[ti]), lo2(kb), a);
                a = ffma2(hi2(qb[ti]), hi2(kb), a);
                r[ti] = a.x + a.y;
            }
            const float w = butterfly8(r, b0, b1, b2);   // lane dd -> ti=dd
            s_s[dd * TIBLK + h * SROW + j] = w;          // conflict-free
        }
    }
    __syncthreads();

    // ===== Phase 1b: s += q.rel ; warp=(ti, jhalf) ==========================
    {
        const int ti = sub;
        float4 qa[HH], qb[HH];
#pragma unroll
        for (int h = 0; h < HH; h++) {
            const float* qp = q + ((size_t)(b * HH + h) * NN + (i0 + ti)) * DKK + dd * 8;
            qa[h] = *(const float4*)qp;
            qb[h] = *(const float4*)(qp + 4);
        }
        const float* rbase = rel + (((size_t)b * NN + (i0 + ti)) * NN) * DKK + dd * 8;
#pragma unroll 2
        for (int s = 0; s < NN / 8; s++) {
            const int j = jo + s * 4 + jj;
            const float* rp = rbase + (size_t)j * DKK;
            const float4 ra = *(const float4*)rp;
            const float4 rb = *(const float4*)(rp + 4);
            float r[HH];
#pragma unroll
            for (int h = 0; h < HH; h++) {
                float2 a = ffma2(lo2(qa[h]), lo2(ra), z2);
                a = ffma2(hi2(qa[h]), hi2(ra), a);
                a = ffma2(lo2(qb[h]), lo2(rb), a);
                a = ffma2(hi2(qb[h]), hi2(rb), a);
                r[h] = a.x + a.y;
            }
            const float w = butterfly8(r, b0, b1, b2);   // lane dd -> h=dd
            s_s[ti * TIBLK + dd * SROW + j] += w;        // conflict-free
        }
    }
    __syncthreads();

    // ===== Softmax: 64 (ti,h) rows, 4 per warp, float4-vectorized ===========
    for (int row = warp; row < TI * HH; row += 16) {
        const int ti = row >> 3;
        const int h  = row & 7;
        const float4* mp4 = (const float4*)(mask +
                            (((size_t)b * HH + h) * NN + (i0 + ti)) * NN);
        float4* sr4 = (float4*)(s_s + ti * TIBLK + h * SROW);
        float4 vals[4];
        float mx = -3.4e38f;
#pragma unroll
        for (int t = 0; t < 4; t++) {
            const int j4 = t * 32 + lane;
            float4 x = sr4[j4];
            const float4 m = mp4[j4];
            x.x += m.x; x.y += m.y; x.z += m.z; x.w += m.w;
            vals[t] = x;
            mx = fmaxf(mx, fmaxf(fmaxf(x.x, x.y), fmaxf(x.z, x.w)));
        }
#pragma unroll
        for (int o = 16; o > 0; o >>= 1)
            mx = fmaxf(mx, __shfl_xor_sync(0xffffffffu, mx, o));
        float sum = 0.f;
#pragma unroll
        for (int t = 0; t < 4; t++) {
            float4 e;
            e.x = __expf(vals[t].x - mx);
            e.y = __expf(vals[t].y - mx);
            e.z = __expf(vals[t].z - mx);
            e.w = __expf(vals[t].w - mx);
            sum += (e.x + e.y) + (e.z + e.w);
            sr4[t * 32 + lane] = e;      // unnormalized p
        }
#pragma unroll
        for (int o = 16; o > 0; o >>= 1)
            sum += __shfl_xor_sync(0xffffffffu, sum, o);
        if (lane == 0) invs[row] = 1.0f / sum;
    }
    __syncthreads();

    // ===== Phase 2b: out2 = p.rel ; warp=(ti, jhalf), j DESCENDING ==========
    {
        const int ti = sub;
        float2 acc[HH][4];
#pragma unroll
        for (int h = 0; h < HH; h++)
#pragma unroll
            for (int c = 0; c < 4; c++) acc[h][c] = z2;

        const float* rbase = rel + (((size_t)b * NN + (i0 + ti)) * NN) * DKK + dd * 8;
#pragma unroll 2
        for (int s = NN / 8 - 1; s >= 0; s--) {
            const int j = jo + s * 4 + jj;
            const float* rp = rbase + (size_t)j * DKK;
            const float4 ra = *(const float4*)rp;
            const float4 rb = *(const float4*)(rp + 4);
#pragma unroll
            for (int h = 0; h < HH; h++) {
                const float p = s_s[ti * TIBLK + h * SROW + j];
                const float2 p2 = make_float2(p, p);
                acc[h][0] = ffma2(p2, lo2(ra), acc[h][0]);
                acc[h][1] = ffma2(p2, hi2(ra), acc[h][1]);
                acc[h][2] = ffma2(p2, lo2(rb), acc[h][2]);
                acc[h][3] = ffma2(p2, hi2(rb), acc[h][3]);
            }
        }
#pragma unroll
        for (int h = 0; h < HH; h++)
#pragma unroll
            for (int c = 0; c < 4; c++) {
                acc[h][c].x += __shfl_xor_sync(0xffffffffu, acc[h][c].x, 8);
                acc[h][c].x += __shfl_xor_sync(0xffffffffu, acc[h][c].x, 16);
                acc[h][c].y += __shfl_xor_sync(0xffffffffu, acc[h][c].y, 8);
                acc[h][c].y += __shfl_xor_sync(0xffffffffu, acc[h][c].y, 16);
            }
        if (jj == 0) {
#pragma unroll
            for (int h = 0; h < HH; h++) {
                float* rp = red2 + ((size_t)jh * TI * HH * DKK) +
                            (ti * HH + h) * DKK + dd * 8;
                *(float4*)rp       = make_float4(acc[h][0].x, acc[h][0].y,
                                                 acc[h][1].x, acc[h][1].y);
                *(float4*)(rp + 4) = make_float4(acc[h][2].x, acc[h][2].y,
                                                 acc[h][3].x, acc[h][3].y);
            }
        }
    }

    // ===== Phase 2a: out1 = p.v ; warp=(h, jhalf) ===========================
    {
        const int h = sub;
        float2 acc[TI][4];
#pragma unroll
        for (int ti = 0; ti < TI; ti++)
#pragma unroll
            for (int c = 0; c < 4; c++) acc[ti][c] = z2;

        const float* vbase = v + ((size_t)(b * HH + h) * NN) * DKK + dd * 8;
#pragma unroll 2
        for (int s = 0; s < NN / 8; s++) {
            const int j = jo + s * 4 + jj;
            const float* vp = vbase + (size_t)j * DKK;
            const float4 va = *(const float4*)vp;
            const float4 vb = *(const float4*)(vp + 4);
#pragma unroll
            for (int ti = 0; ti < TI; ti++) {
                const float p = s_s[ti * TIBLK + h * SROW + j];
                const float2 p2 = make_float2(p, p);
                acc[ti][0] = ffma2(p2, lo2(va), acc[ti][0]);
                acc[ti][1] = ffma2(p2, hi2(va), acc[ti][1]);
                acc[ti][2] = ffma2(p2, lo2(vb), acc[ti][2]);
                acc[ti][3] = ffma2(p2, hi2(vb), acc[ti][3]);
            }
        }
#pragma unroll
        for (int ti = 0; ti < TI; ti++)
#pragma unroll
            for (int c = 0; c < 4; c++) {
                acc[ti][c].x += __shfl_xor_sync(0xffffffffu, acc[ti][c].x, 8);
                acc[ti][c].x += __shfl_xor_sync(0xffffffffu, acc[ti][c].x, 16);
                acc[ti][c].y += __shfl_xor_sync(0xffffffffu, acc[ti][c].y, 8);
                acc[ti][c].y += __shfl_xor_sync(0xffffffffu, acc[ti][c].y, 16);
            }
        if (jj == 0) {
#pragma unroll
            for (int ti = 0; ti < TI; ti++) {
                float* rp = red1 + ((size_t)jh * TI * HH * DKK) +
                            (ti * HH + h) * DKK + dd * 8;
                *(float4*)rp       = make_float4(acc[ti][0].x, acc[ti][0].y,
                                                 acc[ti][1].x, acc[ti][1].y);
                *(float4*)(rp + 4) = make_float4(acc[ti][2].x, acc[ti][2].y,
                                                 acc[ti][3].x, acc[ti][3].y);
            }
        }
    }
    __syncthreads();

    // ===== Combine + normalize + store (float4) =============================
    {
        const int Q = TI * HH * DKK / 4;            // 1024 float4s
        const float4* r14 = (const float4*)red1;
        const float4* r24 = (const float4*)red2;
        for (int idx4 = tid; idx4 < Q; idx4 += NT) {
            const float4 a0 = r14[idx4];
            const float4 a1 = r14[Q + idx4];
            const float4 c0 = r24[idx4];
            const float4 c1 = r24[Q + idx4];
            const int idx = idx4 << 2;
            const int ti = idx >> 9;
            const int h  = (idx >> 6) & 7;
            const int d  = idx & 63;
            const float s = invs[ti * HH + h];
            float4 o;
            o.x = ((a0.x + a1.x) + (c0.x + c1.x)) * s;
            o.y = ((a0.y + a1.y) + (c0.y + c1.y)) * s;
            o.z = ((a0.z + a1.z) + (c0.z + c1.z)) * s;
            o.w = ((a0.w + a1.w) + (c0.w + c1.w)) * s;
            *(float4*)&out[((size_t)(b * HH + h) * NN + (i0 + ti)) * DKK + d] = o;
        }
    }
}

extern "C" void kernel_launch(void* const* d_in, const int* in_sizes, int n_in,
                              void* d_out, int out_size) {
    const float* q    = (const float*)d_in[0];
    const float* k    = (const float*)d_in[1];
    const float* v    = (const float*)d_in[2];
    const float* rel  = (const float*)d_in[3];
    const float* mask = (const float*)d_in[4];
    float* out = (float*)d_out;

    cudaFuncSetAttribute(rel_attn_kernel,
                         cudaFuncAttributeMaxDynamicSharedMemorySize, SMEM_BYTES);
    rel_attn_kernel<<<BB * (NN / TI), NT, SMEM_BYTES>>>(q, k, v, rel, mask, out);
}